// round 14
// baseline (speedup 1.0000x reference)
#include <cuda_runtime.h>
#include <cuda_fp16.h>
#include <cuda_pipeline.h>

#define EPSF 1e-6f
#define EXPERTS 64
#define S_MAX 524288
#define NB 456          // 3 CTAs/SM x 152 SMs exactly (co-residency guaranteed)
#define NT 256
#define ITERS2 9        // iterations 2..10 (iteration 1 fused into prep)

#define TILE_ROWS 128
#define TILE_BYTES (TILE_ROWS * 128)   // 16KB
#define STAGES 2

// Scratch (static device allocations)
__device__ __half2 g_e[(size_t)S_MAX * 32];      // exp(logits - rowmax) fp16, 64MB
__device__ float   g_r[S_MAX];                   // row scale
__device__ __align__(16) float g_c[EXPERTS];     // col scale
__device__ float   g_bpart[EXPERTS * NB];        // per-block column partials
__device__ unsigned g_tick;                      // prep ticket (zero-init, self-reset)
__device__ unsigned g_tickA[ITERS2];             // per-iteration tickets (self-reset)
__device__ unsigned g_gen;                       // generation counter (self-reset)

__device__ __forceinline__ float2 h2f(unsigned u) {
    __half2 h = *reinterpret_cast<__half2*>(&u);
    return __half22float2(h);
}
__device__ __forceinline__ unsigned f2h2(float a, float b) {
    __half2 h = __floats2half2_rn(a, b);
    return *reinterpret_cast<unsigned*>(&h);
}
// fp32 dot of 16 stored fp16 (two uint4) with cq[16] — R6 numerics
__device__ __forceinline__ float dot16(uint4 u0, uint4 u1, const float* cq) {
    float a = 0.f; float2 f;
    f = h2f(u0.x); a = fmaf(f.x, cq[0], a);  a = fmaf(f.y, cq[1], a);
    f = h2f(u0.y); a = fmaf(f.x, cq[2], a);  a = fmaf(f.y, cq[3], a);
    f = h2f(u0.z); a = fmaf(f.x, cq[4], a);  a = fmaf(f.y, cq[5], a);
    f = h2f(u0.w); a = fmaf(f.x, cq[6], a);  a = fmaf(f.y, cq[7], a);
    f = h2f(u1.x); a = fmaf(f.x, cq[8], a);  a = fmaf(f.y, cq[9], a);
    f = h2f(u1.y); a = fmaf(f.x, cq[10], a); a = fmaf(f.y, cq[11], a);
    f = h2f(u1.z); a = fmaf(f.x, cq[12], a); a = fmaf(f.y, cq[13], a);
    f = h2f(u1.w); a = fmaf(f.x, cq[14], a); a = fmaf(f.y, cq[15], a);
    return a;
}
// b[i] += e[i] * rn for 16 fp16, fp32 accumulation — R6 numerics
__device__ __forceinline__ void acc16(uint4 u0, uint4 u1, float rn, float* b) {
    float2 f;
    f = h2f(u0.x); b[0]  = fmaf(f.x, rn, b[0]);  b[1]  = fmaf(f.y, rn, b[1]);
    f = h2f(u0.y); b[2]  = fmaf(f.x, rn, b[2]);  b[3]  = fmaf(f.y, rn, b[3]);
    f = h2f(u0.z); b[4]  = fmaf(f.x, rn, b[4]);  b[5]  = fmaf(f.y, rn, b[5]);
    f = h2f(u0.w); b[6]  = fmaf(f.x, rn, b[6]);  b[7]  = fmaf(f.y, rn, b[7]);
    f = h2f(u1.x); b[8]  = fmaf(f.x, rn, b[8]);  b[9]  = fmaf(f.y, rn, b[9]);
    f = h2f(u1.y); b[10] = fmaf(f.x, rn, b[10]); b[11] = fmaf(f.y, rn, b[11]);
    f = h2f(u1.z); b[12] = fmaf(f.x, rn, b[12]); b[13] = fmaf(f.y, rn, b[13]);
    f = h2f(u1.w); b[14] = fmaf(f.x, rn, b[14]); b[15] = fmaf(f.y, rn, b[15]);
}

// fold 16 float partials across the 8 quads of a warp
#define FOLD8Q(b)                                                              \
    _Pragma("unroll")                                                          \
    for (int o_ = 4; o_ < 32; o_ <<= 1)                                        \
        _Pragma("unroll")                                                      \
        for (int i_ = 0; i_ < 16; i_++)                                        \
            (b)[i_] += __shfl_xor_sync(0xFFFFFFFFu, (b)[i_], o_);

// Last-block reduction for prep (fixed order, deterministic).
__device__ __forceinline__ void tail_finish_prep(float col_target) {
    __shared__ float sq[4][EXPERTS];
    int tid = threadIdx.x;
    int col = tid & 63, qq = tid >> 6;
    float s = 0.f;
    for (int p = qq * (NB / 4); p < (qq + 1) * (NB / 4); p++)
        s += g_bpart[col * NB + p];
    sq[qq][col] = s;
    __syncthreads();
    if (tid < EXPERTS) {
        float btot = sq[0][tid] + sq[1][tid] + sq[2][tid] + sq[3][tid];
        g_c[tid] = col_target / (btot + EPSF);   // c_old = 1
    }
    if (tid == 0) g_tick = 0;
}

// Quad tail for prep.
__device__ __forceinline__ void tail_update_prep(const float* b, float col_target) {
    __shared__ float sb[NT / 32][EXPERTS];
    __shared__ int   slast;
    int tid = threadIdx.x, lane = tid & 31, wid = tid >> 5;
    if (lane < 4) {
        #pragma unroll
        for (int i = 0; i < 16; i++) sb[wid][lane * 16 + i] = b[i];
    }
    __syncthreads();
    if (tid < EXPERTS) {
        float s = 0.f;
        #pragma unroll
        for (int w = 0; w < NT / 32; w++) s += sb[w][tid];
        g_bpart[tid * NB + blockIdx.x] = s;
    }
    __threadfence();
    if (tid == 0) slast = (atomicAdd(&g_tick, 1u) == NB - 1) ? 1 : 0;
    __syncthreads();
    if (slast) tail_finish_prep(col_target);
}

// ---------------------------------------------------------------------------
// K1: prep + Sinkhorn iteration 1 fused. Quad-split (R6 form, grid NB).
// ---------------------------------------------------------------------------
__global__ __launch_bounds__(NT, 3) void k_prep(const float* __restrict__ logits,
                                                int S, float col_target) {
    int tid = threadIdx.x, lane = tid & 31, q = lane & 3;
    float b[16];
    #pragma unroll
    for (int i = 0; i < 16; i++) b[i] = 0.f;

    int gq = (blockIdx.x * NT + tid) >> 2;
    int nq = (NB * NT) >> 2;

    for (int row = gq; row < S; row += nq) {
        const float4* xp = reinterpret_cast<const float4*>(logits)
                           + (size_t)row * 16 + q * 4;
        float4 v0 = __ldcs(xp + 0), v1 = __ldcs(xp + 1);
        float4 v2 = __ldcs(xp + 2), v3 = __ldcs(xp + 3);
        float mx = fmaxf(fmaxf(fmaxf(v0.x, v0.y), fmaxf(v0.z, v0.w)),
                         fmaxf(fmaxf(v1.x, v1.y), fmaxf(v1.z, v1.w)));
        mx = fmaxf(mx, fmaxf(fmaxf(v2.x, v2.y), fmaxf(v2.z, v2.w)));
        mx = fmaxf(mx, fmaxf(fmaxf(v3.x, v3.y), fmaxf(v3.z, v3.w)));
        mx = fmaxf(mx, __shfl_xor_sync(0xFFFFFFFFu, mx, 1));
        mx = fmaxf(mx, __shfl_xor_sync(0xFFFFFFFFu, mx, 2));

        float f[16];
        f[0]  = __expf(v0.x - mx); f[1]  = __expf(v0.y - mx);
        f[2]  = __expf(v0.z - mx); f[3]  = __expf(v0.w - mx);
        f[4]  = __expf(v1.x - mx); f[5]  = __expf(v1.y - mx);
        f[6]  = __expf(v1.z - mx); f[7]  = __expf(v1.w - mx);
        f[8]  = __expf(v2.x - mx); f[9]  = __expf(v2.y - mx);
        f[10] = __expf(v2.z - mx); f[11] = __expf(v2.w - mx);
        f[12] = __expf(v3.x - mx); f[13] = __expf(v3.y - mx);
        f[14] = __expf(v3.z - mx); f[15] = __expf(v3.w - mx);

        float a = 0.f;
        #pragma unroll
        for (int i = 0; i < 16; i++) a += f[i];
        a += __shfl_xor_sync(0xFFFFFFFFu, a, 1);
        a += __shfl_xor_sync(0xFFFFFFFFu, a, 2);

        uint4 e0, e1;
        e0.x = f2h2(f[0], f[1]);   e0.y = f2h2(f[2], f[3]);
        e0.z = f2h2(f[4], f[5]);   e0.w = f2h2(f[6], f[7]);
        e1.x = f2h2(f[8], f[9]);   e1.y = f2h2(f[10], f[11]);
        e1.z = f2h2(f[12], f[13]); e1.w = f2h2(f[14], f[15]);
        uint4* dp = reinterpret_cast<uint4*>(g_e) + (size_t)row * 8 + q * 2;
        dp[0] = e0; dp[1] = e1;

        float rn = __fdividef(1.0f, a + EPSF);
        if (q == 0) g_r[row] = rn;
        acc16(e0, e1, rn, b);
    }
    FOLD8Q(b)
    tail_update_prep(b, col_target);
}

// ---------------------------------------------------------------------------
// K2: ALL remaining Sinkhorn iterations in ONE persistent kernel.
// Grid 456 = exactly 3 resident CTAs/SM x 152 SMs (launch_bounds enforced), so
// a grid-wide generation barrier is deadlock-free. cp.async double-buffer
// streams E tiles CONTINUOUSLY across iterations (E is iteration-invariant).
// Cross-SM data (g_c, g_bpart) read via __ldcg (L2; no stale L1 within the
// persistent launch). g_r is CTA-private. Exact R6/R13 numerics.
// ---------------------------------------------------------------------------
__global__ __launch_bounds__(NT, 3) void k_iter_all(int S, float col_target,
                                                    int iters) {
    __shared__ __align__(16) unsigned char sm[STAGES * TILE_BYTES];
    __shared__ __align__(16) float sc[EXPERTS];
    __shared__ float sb[NT / 32][EXPERTS];
    __shared__ float sq[4][EXPERTS];
    __shared__ int   slast;
    int tid = threadIdx.x, lane = tid & 31, q = lane & 3;
    if (tid < EXPERTS) sc[tid] = __ldcg(&g_c[tid]);
    __syncthreads();

    float cq[16];
    #pragma unroll
    for (int i = 0; i < 16; i++) cq[i] = sc[q * 16 + i];

    int ntiles = S >> 7;
    int grid   = gridDim.x;
    int bid    = blockIdx.x;
    const char* ebase = reinterpret_cast<const char*>(g_e);
    int rit = tid >> 2;                  // row-in-tile (0..63); second row = +64

    int J = (ntiles > bid) ? ((ntiles - 1 - bid) / grid + 1) : 0;

    // prime the pipeline (prefetch cursor runs over the flattened it x j space)
    int pit = 0, pj = 0;
    #pragma unroll
    for (int k2 = 0; k2 < STAGES; k2++) {
        if (pit < iters && J > 0) {
            int t = bid + pj * grid;
            const char* src = ebase + (size_t)t * TILE_BYTES + tid * 16;
            char* dst = (char*)sm + k2 * TILE_BYTES + tid * 16;
            #pragma unroll
            for (int c = 0; c < 4; c++)
                __pipeline_memcpy_async(dst + c * 4096, src + c * 4096, 16);
            if (++pj == J) { pj = 0; pit++; }
        }
        __pipeline_commit();
    }

    int stage = 0;
    for (int it = 0; it < iters; it++) {
        float b[16];
        #pragma unroll
        for (int i = 0; i < 16; i++) b[i] = 0.f;

        for (int j = 0; j < J; j++) {
            int t = bid + j * grid;
            int rowA = (t << 7) + rit;
            int rowB = rowA + 64;
            float rA = g_r[rowA];        // CTA-private: same-SM L1 coherent
            float rB = g_r[rowB];

            __pipeline_wait_prior(STAGES - 1);
            __syncthreads();

            const uint4* tp = reinterpret_cast<const uint4*>(sm + stage * TILE_BYTES);
            uint4 a0 = tp[rit * 8 + q * 2];
            uint4 a1 = tp[rit * 8 + q * 2 + 1];
            uint4 c0 = tp[(rit + 64) * 8 + q * 2];
            uint4 c1 = tp[(rit + 64) * 8 + q * 2 + 1];

            float dA = dot16(a0, a1, cq);
            float dB = dot16(c0, c1, cq);
            dA += __shfl_xor_sync(0xFFFFFFFFu, dA, 1);
            dB += __shfl_xor_sync(0xFFFFFFFFu, dB, 1);
            dA += __shfl_xor_sync(0xFFFFFFFFu, dA, 2);
            dB += __shfl_xor_sync(0xFFFFFFFFu, dB, 2);

            float rnA = __fdividef(rA, fmaf(rA, dA, EPSF));
            float rnB = __fdividef(rB, fmaf(rB, dB, EPSF));
            if (q == 0) g_r[rowA] = rnA;
            if (q == 1) g_r[rowB] = rnB;
            acc16(a0, a1, rnA, b);
            acc16(c0, c1, rnB, b);

            __syncthreads();             // stage fully consumed

            if (pit < iters && J > 0) {  // refill (may belong to NEXT iteration)
                int tn = bid + pj * grid;
                const char* src = ebase + (size_t)tn * TILE_BYTES + tid * 16;
                char* dst = (char*)sm + stage * TILE_BYTES + tid * 16;
                #pragma unroll
                for (int c = 0; c < 4; c++)
                    __pipeline_memcpy_async(dst + c * 4096, src + c * 4096, 16);
                if (++pj == J) { pj = 0; pit++; }
            }
            __pipeline_commit();
            stage ^= 1;
        }

        // tail rows (S % 128): block 0 only, uniform predication.
        int rem0 = ntiles << 7;
        if (rem0 < S && bid == 0) {
            #pragma unroll
            for (int h = 0; h < 2; h++) {
                int row = rem0 + rit + h * 64;
                bool ok = row < S;
                int rowc = ok ? row : (S - 1);
                const uint4* ep = reinterpret_cast<const uint4*>(g_e)
                                  + (size_t)rowc * 8 + q * 2;
                uint4 e0 = ep[0], e1 = ep[1];
                float a = dot16(e0, e1, cq);
                a += __shfl_xor_sync(0xFFFFFFFFu, a, 1);
                a += __shfl_xor_sync(0xFFFFFFFFu, a, 2);
                float ri = g_r[rowc];
                float rn = ok ? __fdividef(ri, fmaf(ri, a, EPSF)) : 0.f;
                if (q == 0 && ok) g_r[rowc] = rn;
                acc16(e0, e1, rn, b);
            }
        }

        FOLD8Q(b)

        // ---- per-iteration global column update + generation barrier ----
        if (lane < 4) {
            int wid = tid >> 5;
            #pragma unroll
            for (int i = 0; i < 16; i++) sb[wid][lane * 16 + i] = b[i];
        }
        __syncthreads();
        if (tid < EXPERTS) {
            float s = 0.f;
            #pragma unroll
            for (int w = 0; w < NT / 32; w++) s += sb[w][tid];
            g_bpart[tid * NB + bid] = s;
        }
        __threadfence();
        if (tid == 0) slast = (atomicAdd(&g_tickA[it], 1u) == NB - 1) ? 1 : 0;
        __syncthreads();

        if (slast) {
            int col = tid & 63, qq2 = tid >> 6;
            float s = 0.f;
            for (int p = qq2 * (NB / 4); p < (qq2 + 1) * (NB / 4); p++)
                s += __ldcg(&g_bpart[col * NB + p]);
            sq[qq2][col] = s;
            __syncthreads();
            if (tid < EXPERTS) {
                float btot = sq[0][tid] + sq[1][tid] + sq[2][tid] + sq[3][tid];
                float c = __ldcg(&g_c[tid]);
                g_c[tid] = c * col_target / (c * btot + EPSF);
            }
            if (tid == 0) {
                if (it < iters - 1) {
                    __threadfence();
                    atomicExch(&g_gen, (unsigned)(it + 1));
                } else {
                    // self-reset for next graph replay (no CTA is waiting now)
                    for (int z = 0; z < iters; z++) g_tickA[z] = 0;
                    __threadfence();
                    g_gen = 0;
                }
            }
        } else if (it < iters - 1) {
            if (tid == 0) {
                while (*((volatile unsigned*)&g_gen) < (unsigned)(it + 1))
                    __nanosleep(64);
            }
        }
        __syncthreads();

        if (it < iters - 1) {
            if (tid < EXPERTS) sc[tid] = __ldcg(&g_c[tid]);
            __syncthreads();
            #pragma unroll
            for (int i = 0; i < 16; i++) cq[i] = sc[q * 16 + i];
        }
    }
}

// ---------------------------------------------------------------------------
// K3: final (k == 2 fast path). Quad-split; fp32 ranking from logits (ldcs).
// Output float32: [idx (S*2)] then [weights (S*2)].
// ---------------------------------------------------------------------------
__global__ __launch_bounds__(NT, 3) void k_final2(const float* __restrict__ logits,
                                                  float* __restrict__ out, int S) {
    __shared__ __align__(16) float sc[EXPERTS];
    int tid = threadIdx.x, lane = tid & 31, q = lane & 3;
    if (tid < EXPERTS) sc[tid] = g_c[tid];
    __syncthreads();

    float cq[16];
    #pragma unroll
    for (int i = 0; i < 16; i++) cq[i] = sc[q * 16 + i];

    int gq = (blockIdx.x * NT + tid) >> 2;
    int nq = (NB * NT) >> 2;

    for (int row = gq; row < S; row += nq) {
        const float4* xp = reinterpret_cast<const float4*>(logits)
                           + (size_t)row * 16 + q * 4;
        float4 v0 = __ldcs(xp + 0), v1 = __ldcs(xp + 1);
        float4 v2 = __ldcs(xp + 2), v3 = __ldcs(xp + 3);
        float mx = fmaxf(fmaxf(fmaxf(v0.x, v0.y), fmaxf(v0.z, v0.w)),
                         fmaxf(fmaxf(v1.x, v1.y), fmaxf(v1.z, v1.w)));
        mx = fmaxf(mx, fmaxf(fmaxf(v2.x, v2.y), fmaxf(v2.z, v2.w)));
        mx = fmaxf(mx, fmaxf(fmaxf(v3.x, v3.y), fmaxf(v3.z, v3.w)));
        mx = fmaxf(mx, __shfl_xor_sync(0xFFFFFFFFu, mx, 1));
        mx = fmaxf(mx, __shfl_xor_sync(0xFFFFFFFFu, mx, 2));

        float u[16];
        u[0]  = __expf(v0.x - mx) * cq[0];  u[1]  = __expf(v0.y - mx) * cq[1];
        u[2]  = __expf(v0.z - mx) * cq[2];  u[3]  = __expf(v0.w - mx) * cq[3];
        u[4]  = __expf(v1.x - mx) * cq[4];  u[5]  = __expf(v1.y - mx) * cq[5];
        u[6]  = __expf(v1.z - mx) * cq[6];  u[7]  = __expf(v1.w - mx) * cq[7];
        u[8]  = __expf(v2.x - mx) * cq[8];  u[9]  = __expf(v2.y - mx) * cq[9];
        u[10] = __expf(v2.z - mx) * cq[10]; u[11] = __expf(v2.w - mx) * cq[11];
        u[12] = __expf(v3.x - mx) * cq[12]; u[13] = __expf(v3.y - mx) * cq[13];
        u[14] = __expf(v3.z - mx) * cq[14]; u[15] = __expf(v3.w - mx) * cq[15];

        float A = 0.f;
        float m1 = -1.f, m2 = -1.f, i1 = 0.f, i2 = 0.f;
        #pragma unroll
        for (int t = 0; t < 16; t++) {
            A += u[t];
            float jj = (float)(q * 16 + t);
            bool g1 = u[t] > m1, g2 = u[t] > m2;
            m2 = g1 ? m1 : (g2 ? u[t] : m2);
            i2 = g1 ? i1 : (g2 ? jj : i2);
            m1 = g1 ? u[t] : m1;
            i1 = g1 ? jj : i1;
        }
        A += __shfl_xor_sync(0xFFFFFFFFu, A, 1);
        A += __shfl_xor_sync(0xFFFFFFFFu, A, 2);

        #pragma unroll
        for (int o = 1; o <= 2; o <<= 1) {
            float om1 = __shfl_xor_sync(0xFFFFFFFFu, m1, o);
            float oi1 = __shfl_xor_sync(0xFFFFFFFFu, i1, o);
            float om2 = __shfl_xor_sync(0xFFFFFFFFu, m2, o);
            float oi2 = __shfl_xor_sync(0xFFFFFFFFu, i2, o);
            if (om1 > m1) {
                bool keep = (m1 >= om2);
                m2 = keep ? m1 : om2;
                i2 = keep ? i1 : oi2;
                m1 = om1; i1 = oi1;
            } else if (om1 > m2) {
                m2 = om1; i2 = oi1;
            }
        }

        if (q == 0) {
            float ri  = g_r[row];
            float t   = __fdividef(ri, fmaf(ri, A, EPSF));
            float w1  = m1 * t, w2 = m2 * t;
            float inv = __fdividef(1.0f, w1 + w2 + EPSF);
            reinterpret_cast<float2*>(out)[row] = make_float2(i1, i2);
            reinterpret_cast<float2*>(out)[(size_t)S + row] =
                make_float2(w1 * inv, w2 * inv);
        }
    }
}

// ---------------------------------------------------------------------------
// Generic fallback (k != 2): warp-per-row (known-correct R3 code)
// ---------------------------------------------------------------------------
__global__ void k_final_gen(const float* __restrict__ logits,
                            float* __restrict__ out, int S, int k, size_t out_n) {
    int lane = threadIdx.x & 31;
    int warp = (blockIdx.x * blockDim.x + threadIdx.x) >> 5;
    int nw   = (gridDim.x * blockDim.x) >> 5;
    float2 cc = ((const float2*)g_c)[lane];

    for (int row = warp; row < S; row += nw) {
        float2 x = ((const float2*)logits)[(size_t)row * 32 + lane];
        float m = fmaxf(x.x, x.y);
        #pragma unroll
        for (int o = 16; o; o >>= 1) m = fmaxf(m, __shfl_xor_sync(0xFFFFFFFFu, m, o));
        float u0 = __expf(x.x - m) * cc.x;
        float u1 = __expf(x.y - m) * cc.y;
        float A = u0 + u1;
        #pragma unroll
        for (int o = 16; o; o >>= 1) A += __shfl_xor_sync(0xFFFFFFFFu, A, o);
        float ri = g_r[row];
        float denom = ri * A + EPSF;
        float lu0 = u0, lu1 = u1;
        float vals[8]; int idxs[8];
        for (int t = 0; t < k; t++) {
            float lv; int li;
            if (lu0 >= lu1) { lv = lu0; li = 2 * lane; }
            else            { lv = lu1; li = 2 * lane + 1; }
            #pragma unroll
            for (int o = 16; o; o >>= 1) {
                float ov = __shfl_xor_sync(0xFFFFFFFFu, lv, o);
                int   oi = __shfl_xor_sync(0xFFFFFFFFu, li, o);
                if (ov > lv || (ov == lv && oi < li)) { lv = ov; li = oi; }
            }
            vals[t] = lv; idxs[t] = li;
            if (li == 2 * lane)     lu0 = -1.f;
            if (li == 2 * lane + 1) lu1 = -1.f;
        }
        if (lane == 0) {
            float v[8], vs = 0.f;
            for (int t = 0; t < k; t++) { v[t] = ri * vals[t] / denom; vs += v[t]; }
            float inv = 1.0f / (vs + EPSF);
            for (int t = 0; t < k; t++) {
                size_t pi = (size_t)row * k + t;
                size_t pw = (size_t)S * k + pi;
                if (pi < out_n) out[pi] = (float)idxs[t];
                if (pw < out_n) out[pw] = v[t] * inv;
            }
        }
    }
}

// ---------------------------------------------------------------------------
extern "C" void kernel_launch(void* const* d_in, const int* in_sizes, int n_in,
                              void* d_out, int out_size) {
    const float* logits = (const float*)d_in[0];
    float*       out    = (float*)d_out;

    int S = in_sizes[0] / EXPERTS;
    if (S > S_MAX) S = S_MAX;
    if (S < 1) S = 1;
    float col_target = (float)S / (float)EXPERTS;

    int k = (int)((size_t)out_size / (2 * (size_t)S));
    if (k < 1) k = 1;
    if (k > 8) k = 8;

    k_prep<<<NB, NT>>>(logits, S, col_target);          // includes iteration 1
    k_iter_all<<<NB, NT>>>(S, col_target, ITERS2);      // iterations 2..10 fused
    if (k == 2)
        k_final2<<<NB, NT>>>(logits, out, S);
    else
        k_final_gen<<<4096, 256>>>(logits, out, S, k, (size_t)out_size);
}

// round 15
// speedup vs baseline: 1.3890x; 1.3890x over previous
#include <cuda_runtime.h>
#include <cuda_fp16.h>
#include <cuda_pipeline.h>

#define EPSF 1e-6f
#define EXPERTS 64
#define S_MAX 524288
#define NB 456          // 3 CTAs/SM x 152 SMs, divisible by 4
#define NT 256

#define TILE_ROWS 64
#define TILE_BYTES (TILE_ROWS * 128)   // 8KB
#define STAGES 5                        // 4 groups in flight, 1 sync/tile

// Scratch (static device allocations)
__device__ __half2 g_e[(size_t)S_MAX * 32];      // exp(logits - rowmax) fp16, 64MB
__device__ float   g_r[S_MAX];                   // row scale
__device__ __align__(16) float g_c[EXPERTS];     // col scale
__device__ float   g_bpart[EXPERTS * NB];        // per-block column partials
__device__ unsigned g_tick;                      // last-block ticket (self-reset)

__device__ __forceinline__ float2 h2f(unsigned u) {
    __half2 h = *reinterpret_cast<__half2*>(&u);
    return __half22float2(h);
}
__device__ __forceinline__ unsigned f2h2(float a, float b) {
    __half2 h = __floats2half2_rn(a, b);
    return *reinterpret_cast<unsigned*>(&h);
}
// fp32 dot of 16 stored fp16 (two uint4) with cq[16] — R6 numerics
__device__ __forceinline__ float dot16(uint4 u0, uint4 u1, const float* cq) {
    float a = 0.f; float2 f;
    f = h2f(u0.x); a = fmaf(f.x, cq[0], a);  a = fmaf(f.y, cq[1], a);
    f = h2f(u0.y); a = fmaf(f.x, cq[2], a);  a = fmaf(f.y, cq[3], a);
    f = h2f(u0.z); a = fmaf(f.x, cq[4], a);  a = fmaf(f.y, cq[5], a);
    f = h2f(u0.w); a = fmaf(f.x, cq[6], a);  a = fmaf(f.y, cq[7], a);
    f = h2f(u1.x); a = fmaf(f.x, cq[8], a);  a = fmaf(f.y, cq[9], a);
    f = h2f(u1.y); a = fmaf(f.x, cq[10], a); a = fmaf(f.y, cq[11], a);
    f = h2f(u1.z); a = fmaf(f.x, cq[12], a); a = fmaf(f.y, cq[13], a);
    f = h2f(u1.w); a = fmaf(f.x, cq[14], a); a = fmaf(f.y, cq[15], a);
    return a;
}
// b[i] += e[i] * rn for 16 fp16, fp32 accumulation — R6 numerics
__device__ __forceinline__ void acc16(uint4 u0, uint4 u1, float rn, float* b) {
    float2 f;
    f = h2f(u0.x); b[0]  = fmaf(f.x, rn, b[0]);  b[1]  = fmaf(f.y, rn, b[1]);
    f = h2f(u0.y); b[2]  = fmaf(f.x, rn, b[2]);  b[3]  = fmaf(f.y, rn, b[3]);
    f = h2f(u0.z); b[4]  = fmaf(f.x, rn, b[4]);  b[5]  = fmaf(f.y, rn, b[5]);
    f = h2f(u0.w); b[6]  = fmaf(f.x, rn, b[6]);  b[7]  = fmaf(f.y, rn, b[7]);
    f = h2f(u1.x); b[8]  = fmaf(f.x, rn, b[8]);  b[9]  = fmaf(f.y, rn, b[9]);
    f = h2f(u1.y); b[10] = fmaf(f.x, rn, b[10]); b[11] = fmaf(f.y, rn, b[11]);
    f = h2f(u1.z); b[12] = fmaf(f.x, rn, b[12]); b[13] = fmaf(f.y, rn, b[13]);
    f = h2f(u1.w); b[14] = fmaf(f.x, rn, b[14]); b[15] = fmaf(f.y, rn, b[15]);
}

// Last-block reduction (fixed order, deterministic).
__device__ __forceinline__ void tail_finish(float col_target, bool first) {
    __shared__ float sq[4][EXPERTS];
    int tid = threadIdx.x;
    int col = tid & 63, qq = tid >> 6;
    float s = 0.f;
    for (int p = qq * (NB / 4); p < (qq + 1) * (NB / 4); p++)
        s += g_bpart[col * NB + p];
    sq[qq][col] = s;
    __syncthreads();
    if (tid < EXPERTS) {
        float btot = sq[0][tid] + sq[1][tid] + sq[2][tid] + sq[3][tid];
        float c = first ? 1.0f : g_c[tid];
        g_c[tid] = c * col_target / (c * btot + EPSF);
    }
    if (tid == 0) g_tick = 0;
}

// Quad tail: lane q of each quad owns cols q*16..q*16+15 (warp-folded).
__device__ __forceinline__ void tail_update_q(const float* b, float col_target,
                                              bool first) {
    __shared__ float sb[NT / 32][EXPERTS];
    __shared__ int   slast;
    int tid = threadIdx.x, lane = tid & 31, wid = tid >> 5;
    if (lane < 4) {
        #pragma unroll
        for (int i = 0; i < 16; i++) sb[wid][lane * 16 + i] = b[i];
    }
    __syncthreads();
    if (tid < EXPERTS) {
        float s = 0.f;
        #pragma unroll
        for (int w = 0; w < NT / 32; w++) s += sb[w][tid];
        g_bpart[tid * NB + blockIdx.x] = s;
    }
    __threadfence();
    if (tid == 0) slast = (atomicAdd(&g_tick, 1u) == NB - 1) ? 1 : 0;
    __syncthreads();
    if (slast) tail_finish(col_target, first);
}

// fold 16 float partials across the 8 quads of a warp
#define FOLD8Q(b)                                                              \
    _Pragma("unroll")                                                          \
    for (int o_ = 4; o_ < 32; o_ <<= 1)                                        \
        _Pragma("unroll")                                                      \
        for (int i_ = 0; i_ < 16; i_++)                                        \
            (b)[i_] += __shfl_xor_sync(0xFFFFFFFFu, (b)[i_], o_);

// ---------------------------------------------------------------------------
// K1: prep + Sinkhorn iteration 1 fused. Quad-split (R6 form, grid NB).
// ---------------------------------------------------------------------------
__global__ __launch_bounds__(NT, 3) void k_prep(const float* __restrict__ logits,
                                                int S, float col_target) {
    int tid = threadIdx.x, lane = tid & 31, q = lane & 3;
    float b[16];
    #pragma unroll
    for (int i = 0; i < 16; i++) b[i] = 0.f;

    int gq = (blockIdx.x * NT + tid) >> 2;
    int nq = (NB * NT) >> 2;

    for (int row = gq; row < S; row += nq) {
        const float4* xp = reinterpret_cast<const float4*>(logits)
                           + (size_t)row * 16 + q * 4;
        float4 v0 = __ldcs(xp + 0), v1 = __ldcs(xp + 1);
        float4 v2 = __ldcs(xp + 2), v3 = __ldcs(xp + 3);
        float mx = fmaxf(fmaxf(fmaxf(v0.x, v0.y), fmaxf(v0.z, v0.w)),
                         fmaxf(fmaxf(v1.x, v1.y), fmaxf(v1.z, v1.w)));
        mx = fmaxf(mx, fmaxf(fmaxf(v2.x, v2.y), fmaxf(v2.z, v2.w)));
        mx = fmaxf(mx, fmaxf(fmaxf(v3.x, v3.y), fmaxf(v3.z, v3.w)));
        mx = fmaxf(mx, __shfl_xor_sync(0xFFFFFFFFu, mx, 1));
        mx = fmaxf(mx, __shfl_xor_sync(0xFFFFFFFFu, mx, 2));

        float f[16];
        f[0]  = __expf(v0.x - mx); f[1]  = __expf(v0.y - mx);
        f[2]  = __expf(v0.z - mx); f[3]  = __expf(v0.w - mx);
        f[4]  = __expf(v1.x - mx); f[5]  = __expf(v1.y - mx);
        f[6]  = __expf(v1.z - mx); f[7]  = __expf(v1.w - mx);
        f[8]  = __expf(v2.x - mx); f[9]  = __expf(v2.y - mx);
        f[10] = __expf(v2.z - mx); f[11] = __expf(v2.w - mx);
        f[12] = __expf(v3.x - mx); f[13] = __expf(v3.y - mx);
        f[14] = __expf(v3.z - mx); f[15] = __expf(v3.w - mx);

        float a = 0.f;
        #pragma unroll
        for (int i = 0; i < 16; i++) a += f[i];
        a += __shfl_xor_sync(0xFFFFFFFFu, a, 1);
        a += __shfl_xor_sync(0xFFFFFFFFu, a, 2);

        uint4 e0, e1;
        e0.x = f2h2(f[0], f[1]);   e0.y = f2h2(f[2], f[3]);
        e0.z = f2h2(f[4], f[5]);   e0.w = f2h2(f[6], f[7]);
        e1.x = f2h2(f[8], f[9]);   e1.y = f2h2(f[10], f[11]);
        e1.z = f2h2(f[12], f[13]); e1.w = f2h2(f[14], f[15]);
        uint4* dp = reinterpret_cast<uint4*>(g_e) + (size_t)row * 8 + q * 2;
        dp[0] = e0; dp[1] = e1;

        float rn = __fdividef(1.0f, a + EPSF);
        if (q == 0) g_r[row] = rn;
        acc16(e0, e1, rn, b);   // from quantized values (matches iteration reads)
    }
    FOLD8Q(b)
    tail_update_q(b, col_target, true);
}

// ---------------------------------------------------------------------------
// K2: one Sinkhorn iteration — cp.async 5-stage pipeline, 64-row (8KB) tiles,
// ONE __syncthreads per tile. At tile j we refill the slot computed at j-1:
// the top-of-tile sync proves all warps finished it (valid for STAGES >= 3).
// 4 groups (32KB) in flight during compute. Exact R6/R13 per-row numerics.
// ---------------------------------------------------------------------------
__global__ __launch_bounds__(NT, 3) void k_iter(int S, float col_target) {
    __shared__ __align__(16) unsigned char sm[STAGES * TILE_BYTES];
    __shared__ __align__(16) float sc[EXPERTS];
    int tid = threadIdx.x, lane = tid & 31, q = lane & 3;
    if (tid < EXPERTS) sc[tid] = g_c[tid];
    __syncthreads();

    float cq[16];
    #pragma unroll
    for (int i = 0; i < 16; i++) cq[i] = sc[q * 16 + i];
    float b[16];
    #pragma unroll
    for (int i = 0; i < 16; i++) b[i] = 0.f;

    int ntiles = S >> 6;                 // full 64-row tiles
    int grid   = gridDim.x;
    int bid    = blockIdx.x;
    const char* ebase = reinterpret_cast<const char*>(g_e);
    int rit = tid >> 2;                  // row-in-tile (0..63)

    // number of tiles this CTA owns (tile index = bid + j*grid)
    int J = (ntiles > bid) ? ((ntiles - 1 - bid) / grid + 1) : 0;

    // prologue: load tiles j=0..STAGES-2 into slots 0..STAGES-2
    #pragma unroll
    for (int k = 0; k < STAGES - 1; k++) {
        if (k < J) {
            int t = bid + k * grid;
            const char* src = ebase + (size_t)t * TILE_BYTES + tid * 16;
            char* dst = (char*)sm + k * TILE_BYTES + tid * 16;
            __pipeline_memcpy_async(dst, src, 16);
            __pipeline_memcpy_async(dst + 4096, src + 4096, 16);
        }
        __pipeline_commit();
    }

    for (int j = 0; j < J; j++) {
        int t   = bid + j * grid;
        int row = (t << 6) + rit;
        float ri = g_r[row];             // hoisted before the wait

        __pipeline_wait_prior(STAGES - 2);   // group j (oldest) complete
        __syncthreads();                      // all warps left slot (j-1)%STAGES

        int slot = j % STAGES;
        const uint4* tp = reinterpret_cast<const uint4*>(sm + slot * TILE_BYTES);
        uint4 e0 = tp[rit * 8 + q * 2];
        uint4 e1 = tp[rit * 8 + q * 2 + 1];

        float a = dot16(e0, e1, cq);
        a += __shfl_xor_sync(0xFFFFFFFFu, a, 1);
        a += __shfl_xor_sync(0xFFFFFFFFu, a, 2);

        float rn = __fdividef(ri, fmaf(ri, a, EPSF));
        if (q == 0) g_r[row] = rn;
        acc16(e0, e1, rn, b);

        // refill tile j+STAGES-1 into slot (j-1)%STAGES (safe per the sync above)
        int jn = j + STAGES - 1;
        if (jn < J) {
            int tn = bid + jn * grid;
            int sn = jn % STAGES;        // == (j-1) % STAGES
            const char* src = ebase + (size_t)tn * TILE_BYTES + tid * 16;
            char* dst = (char*)sm + sn * TILE_BYTES + tid * 16;
            __pipeline_memcpy_async(dst, src, 16);
            __pipeline_memcpy_async(dst + 4096, src + 4096, 16);
        }
        __pipeline_commit();
    }

    // tail rows (S % 64): block 0 only, uniform predication.
    int rem0 = ntiles << 6;
    if (rem0 < S && bid == 0) {
        int row = rem0 + rit;
        bool ok = row < S;
        int rowc = ok ? row : (S - 1);
        const uint4* ep = reinterpret_cast<const uint4*>(g_e)
                          + (size_t)rowc * 8 + q * 2;
        uint4 e0 = ep[0], e1 = ep[1];
        float a = dot16(e0, e1, cq);
        a += __shfl_xor_sync(0xFFFFFFFFu, a, 1);
        a += __shfl_xor_sync(0xFFFFFFFFu, a, 2);
        float ri = g_r[rowc];
        float rn = ok ? __fdividef(ri, fmaf(ri, a, EPSF)) : 0.f;
        if (q == 0 && ok) g_r[rowc] = rn;
        acc16(e0, e1, rn, b);
    }

    FOLD8Q(b)
    tail_update_q(b, col_target, false);
}

// ---------------------------------------------------------------------------
// K3: final (k == 2 fast path). Quad-split; fp32 ranking from logits (ldcs).
// Output float32: [idx (S*2)] then [weights (S*2)].
// ---------------------------------------------------------------------------
__global__ __launch_bounds__(NT, 3) void k_final2(const float* __restrict__ logits,
                                                  float* __restrict__ out, int S) {
    __shared__ __align__(16) float sc[EXPERTS];
    int tid = threadIdx.x, lane = tid & 31, q = lane & 3;
    if (tid < EXPERTS) sc[tid] = g_c[tid];
    __syncthreads();

    float cq[16];
    #pragma unroll
    for (int i = 0; i < 16; i++) cq[i] = sc[q * 16 + i];

    int gq = (blockIdx.x * NT + tid) >> 2;
    int nq = (NB * NT) >> 2;

    for (int row = gq; row < S; row += nq) {
        const float4* xp = reinterpret_cast<const float4*>(logits)
                           + (size_t)row * 16 + q * 4;
        float4 v0 = __ldcs(xp + 0), v1 = __ldcs(xp + 1);
        float4 v2 = __ldcs(xp + 2), v3 = __ldcs(xp + 3);
        float mx = fmaxf(fmaxf(fmaxf(v0.x, v0.y), fmaxf(v0.z, v0.w)),
                         fmaxf(fmaxf(v1.x, v1.y), fmaxf(v1.z, v1.w)));
        mx = fmaxf(mx, fmaxf(fmaxf(v2.x, v2.y), fmaxf(v2.z, v2.w)));
        mx = fmaxf(mx, fmaxf(fmaxf(v3.x, v3.y), fmaxf(v3.z, v3.w)));
        mx = fmaxf(mx, __shfl_xor_sync(0xFFFFFFFFu, mx, 1));
        mx = fmaxf(mx, __shfl_xor_sync(0xFFFFFFFFu, mx, 2));

        float u[16];
        u[0]  = __expf(v0.x - mx) * cq[0];  u[1]  = __expf(v0.y - mx) * cq[1];
        u[2]  = __expf(v0.z - mx) * cq[2];  u[3]  = __expf(v0.w - mx) * cq[3];
        u[4]  = __expf(v1.x - mx) * cq[4];  u[5]  = __expf(v1.y - mx) * cq[5];
        u[6]  = __expf(v1.z - mx) * cq[6];  u[7]  = __expf(v1.w - mx) * cq[7];
        u[8]  = __expf(v2.x - mx) * cq[8];  u[9]  = __expf(v2.y - mx) * cq[9];
        u[10] = __expf(v2.z - mx) * cq[10]; u[11] = __expf(v2.w - mx) * cq[11];
        u[12] = __expf(v3.x - mx) * cq[12]; u[13] = __expf(v3.y - mx) * cq[13];
        u[14] = __expf(v3.z - mx) * cq[14]; u[15] = __expf(v3.w - mx) * cq[15];

        float A = 0.f;
        float m1 = -1.f, m2 = -1.f, i1 = 0.f, i2 = 0.f;
        #pragma unroll
        for (int t = 0; t < 16; t++) {
            A += u[t];
            float jj = (float)(q * 16 + t);
            bool g1 = u[t] > m1, g2 = u[t] > m2;
            m2 = g1 ? m1 : (g2 ? u[t] : m2);
            i2 = g1 ? i1 : (g2 ? jj : i2);
            m1 = g1 ? u[t] : m1;
            i1 = g1 ? jj : i1;
        }
        A += __shfl_xor_sync(0xFFFFFFFFu, A, 1);
        A += __shfl_xor_sync(0xFFFFFFFFu, A, 2);

        #pragma unroll
        for (int o = 1; o <= 2; o <<= 1) {
            float om1 = __shfl_xor_sync(0xFFFFFFFFu, m1, o);
            float oi1 = __shfl_xor_sync(0xFFFFFFFFu, i1, o);
            float om2 = __shfl_xor_sync(0xFFFFFFFFu, m2, o);
            float oi2 = __shfl_xor_sync(0xFFFFFFFFu, i2, o);
            if (om1 > m1) {
                bool keep = (m1 >= om2);
                m2 = keep ? m1 : om2;
                i2 = keep ? i1 : oi2;
                m1 = om1; i1 = oi1;
            } else if (om1 > m2) {
                m2 = om1; i2 = oi1;
            }
        }

        if (q == 0) {
            float ri  = g_r[row];
            float t   = __fdividef(ri, fmaf(ri, A, EPSF));
            float w1  = m1 * t, w2 = m2 * t;
            float inv = __fdividef(1.0f, w1 + w2 + EPSF);
            reinterpret_cast<float2*>(out)[row] = make_float2(i1, i2);
            reinterpret_cast<float2*>(out)[(size_t)S + row] =
                make_float2(w1 * inv, w2 * inv);
        }
    }
}

// ---------------------------------------------------------------------------
// Generic fallback (k != 2): warp-per-row (known-correct R3 code)
// ---------------------------------------------------------------------------
__global__ void k_final_gen(const float* __restrict__ logits,
                            float* __restrict__ out, int S, int k, size_t out_n) {
    int lane = threadIdx.x & 31;
    int warp = (blockIdx.x * blockDim.x + threadIdx.x) >> 5;
    int nw   = (gridDim.x * blockDim.x) >> 5;
    float2 cc = ((const float2*)g_c)[lane];

    for (int row = warp; row < S; row += nw) {
        float2 x = ((const float2*)logits)[(size_t)row * 32 + lane];
        float m = fmaxf(x.x, x.y);
        #pragma unroll
        for (int o = 16; o; o >>= 1) m = fmaxf(m, __shfl_xor_sync(0xFFFFFFFFu, m, o));
        float u0 = __expf(x.x - m) * cc.x;
        float u1 = __expf(x.y - m) * cc.y;
        float A = u0 + u1;
        #pragma unroll
        for (int o = 16; o; o >>= 1) A += __shfl_xor_sync(0xFFFFFFFFu, A, o);
        float ri = g_r[row];
        float denom = ri * A + EPSF;
        float lu0 = u0, lu1 = u1;
        float vals[8]; int idxs[8];
        for (int t = 0; t < k; t++) {
            float lv; int li;
            if (lu0 >= lu1) { lv = lu0; li = 2 * lane; }
            else            { lv = lu1; li = 2 * lane + 1; }
            #pragma unroll
            for (int o = 16; o; o >>= 1) {
                float ov = __shfl_xor_sync(0xFFFFFFFFu, lv, o);
                int   oi = __shfl_xor_sync(0xFFFFFFFFu, li, o);
                if (ov > lv || (ov == lv && oi < li)) { lv = ov; li = oi; }
            }
            vals[t] = lv; idxs[t] = li;
            if (li == 2 * lane)     lu0 = -1.f;
            if (li == 2 * lane + 1) lu1 = -1.f;
        }
        if (lane == 0) {
            float v[8], vs = 0.f;
            for (int t = 0; t < k; t++) { v[t] = ri * vals[t] / denom; vs += v[t]; }
            float inv = 1.0f / (vs + EPSF);
            for (int t = 0; t < k; t++) {
                size_t pi = (size_t)row * k + t;
                size_t pw = (size_t)S * k + pi;
                if (pi < out_n) out[pi] = (float)idxs[t];
                if (pw < out_n) out[pw] = v[t] * inv;
            }
        }
    }
}

// ---------------------------------------------------------------------------
extern "C" void kernel_launch(void* const* d_in, const int* in_sizes, int n_in,
                              void* d_out, int out_size) {
    const float* logits = (const float*)d_in[0];
    float*       out    = (float*)d_out;

    int S = in_sizes[0] / EXPERTS;
    if (S > S_MAX) S = S_MAX;
    if (S < 1) S = 1;
    float col_target = (float)S / (float)EXPERTS;

    int k = (int)((size_t)out_size / (2 * (size_t)S));
    if (k < 1) k = 1;
    if (k > 8) k = 8;

    k_prep<<<NB, NT>>>(logits, S, col_target);          // includes iteration 1
    for (int it = 1; it < 10; it++)
        k_iter<<<NB, NT>>>(S, col_target);              // iterations 2..10
    if (k == 2)
        k_final2<<<NB, NT>>>(logits, out, S);
    else
        k_final_gen<<<4096, 256>>>(logits, out, S, k, (size_t)out_size);
}

// round 17
// speedup vs baseline: 1.4451x; 1.0404x over previous
#include <cuda_runtime.h>
#include <cuda_fp16.h>
#include <cuda_pipeline.h>

#define EPSF 1e-6f
#define EXPERTS 64
#define S_MAX 524288
#define NB 456          // 3 CTAs/SM x 152 SMs, divisible by 4
#define NT 256

#define TILE_ROWS 128
#define TILE_BYTES (TILE_ROWS * 128)   // 16KB
#define STAGES 2

// Scratch (static device allocations)
__device__ __half2 g_e[(size_t)S_MAX * 32];      // exp(logits - rowmax) fp16, 64MB (128B/row)
__device__ float   g_r[S_MAX];                   // row scale
__device__ __align__(16) float g_c[EXPERTS];     // col scale
__device__ float   g_bpart[EXPERTS * NB];        // per-block column partials
__device__ unsigned g_tick;                      // last-block ticket (zero-init, self-reset)

__device__ __forceinline__ float2 h2f(unsigned u) {
    __half2 h = *reinterpret_cast<__half2*>(&u);
    return __half22float2(h);
}
__device__ __forceinline__ unsigned f2h2(float a, float b) {
    __half2 h = __floats2half2_rn(a, b);
    return *reinterpret_cast<unsigned*>(&h);
}
// fp32 dot of 16 stored fp16 (two uint4) with cq[16] — R6 numerics
__device__ __forceinline__ float dot16(uint4 u0, uint4 u1, const float* cq) {
    float a = 0.f; float2 f;
    f = h2f(u0.x); a = fmaf(f.x, cq[0], a);  a = fmaf(f.y, cq[1], a);
    f = h2f(u0.y); a = fmaf(f.x, cq[2], a);  a = fmaf(f.y, cq[3], a);
    f = h2f(u0.z); a = fmaf(f.x, cq[4], a);  a = fmaf(f.y, cq[5], a);
    f = h2f(u0.w); a = fmaf(f.x, cq[6], a);  a = fmaf(f.y, cq[7], a);
    f = h2f(u1.x); a = fmaf(f.x, cq[8], a);  a = fmaf(f.y, cq[9], a);
    f = h2f(u1.y); a = fmaf(f.x, cq[10], a); a = fmaf(f.y, cq[11], a);
    f = h2f(u1.z); a = fmaf(f.x, cq[12], a); a = fmaf(f.y, cq[13], a);
    f = h2f(u1.w); a = fmaf(f.x, cq[14], a); a = fmaf(f.y, cq[15], a);
    return a;
}
// b[i] += e[i] * rn for 16 fp16, fp32 accumulation — R6 numerics
__device__ __forceinline__ void acc16(uint4 u0, uint4 u1, float rn, float* b) {
    float2 f;
    f = h2f(u0.x); b[0]  = fmaf(f.x, rn, b[0]);  b[1]  = fmaf(f.y, rn, b[1]);
    f = h2f(u0.y); b[2]  = fmaf(f.x, rn, b[2]);  b[3]  = fmaf(f.y, rn, b[3]);
    f = h2f(u0.z); b[4]  = fmaf(f.x, rn, b[4]);  b[5]  = fmaf(f.y, rn, b[5]);
    f = h2f(u0.w); b[6]  = fmaf(f.x, rn, b[6]);  b[7]  = fmaf(f.y, rn, b[7]);
    f = h2f(u1.x); b[8]  = fmaf(f.x, rn, b[8]);  b[9]  = fmaf(f.y, rn, b[9]);
    f = h2f(u1.y); b[10] = fmaf(f.x, rn, b[10]); b[11] = fmaf(f.y, rn, b[11]);
    f = h2f(u1.z); b[12] = fmaf(f.x, rn, b[12]); b[13] = fmaf(f.y, rn, b[13]);
    f = h2f(u1.w); b[14] = fmaf(f.x, rn, b[14]); b[15] = fmaf(f.y, rn, b[15]);
}

// Last-block reduction (fixed order, deterministic).
__device__ __forceinline__ void tail_finish(float col_target, bool first) {
    __shared__ float sq[4][EXPERTS];
    int tid = threadIdx.x;
    int col = tid & 63, qq = tid >> 6;
    float s = 0.f;
    for (int p = qq * (NB / 4); p < (qq + 1) * (NB / 4); p++)
        s += g_bpart[col * NB + p];
    sq[qq][col] = s;
    __syncthreads();
    if (tid < EXPERTS) {
        float btot = sq[0][tid] + sq[1][tid] + sq[2][tid] + sq[3][tid];
        float c = first ? 1.0f : g_c[tid];
        g_c[tid] = c * col_target / (c * btot + EPSF);
    }
    if (tid == 0) g_tick = 0;
}

// Quad tail: lane q of each quad owns cols q*16..q*16+15 (warp-folded).
__device__ __forceinline__ void tail_update_q(const float* b, float col_target,
                                              bool first) {
    __shared__ float sb[NT / 32][EXPERTS];
    __shared__ int   slast;
    int tid = threadIdx.x, lane = tid & 31, wid = tid >> 5;
    if (lane < 4) {
        #pragma unroll
        for (int i = 0; i < 16; i++) sb[wid][lane * 16 + i] = b[i];
    }
    __syncthreads();
    if (tid < EXPERTS) {
        float s = 0.f;
        #pragma unroll
        for (int w = 0; w < NT / 32; w++) s += sb[w][tid];
        g_bpart[tid * NB + blockIdx.x] = s;
    }
    __threadfence();
    if (tid == 0) slast = (atomicAdd(&g_tick, 1u) == NB - 1) ? 1 : 0;
    __syncthreads();
    if (slast) tail_finish(col_target, first);
}

// fold 16 float partials across the 8 quads of a warp
#define FOLD8Q(b)                                                              \
    _Pragma("unroll")                                                          \
    for (int o_ = 4; o_ < 32; o_ <<= 1)                                        \
        _Pragma("unroll")                                                      \
        for (int i_ = 0; i_ < 16; i_++)                                        \
            (b)[i_] += __shfl_xor_sync(0xFFFFFFFFu, (b)[i_], o_);

// ---------------------------------------------------------------------------
// K1: prep + Sinkhorn iteration 1 fused. Quad-split: 4 threads per row,
// thread q handles columns [q*16, q*16+16). Logits streamed (evict-first).
// ---------------------------------------------------------------------------
__global__ __launch_bounds__(NT, 3) void k_prep(const float* __restrict__ logits,
                                                int S, float col_target) {
    int tid = threadIdx.x, lane = tid & 31, q = lane & 3;
    float b[16];
    #pragma unroll
    for (int i = 0; i < 16; i++) b[i] = 0.f;

    int gq = (blockIdx.x * NT + tid) >> 2;
    int nq = (NB * NT) >> 2;

    for (int row = gq; row < S; row += nq) {
        const float4* xp = reinterpret_cast<const float4*>(logits)
                           + (size_t)row * 16 + q * 4;
        float4 v0 = __ldcs(xp + 0), v1 = __ldcs(xp + 1);
        float4 v2 = __ldcs(xp + 2), v3 = __ldcs(xp + 3);
        float mx = fmaxf(fmaxf(fmaxf(v0.x, v0.y), fmaxf(v0.z, v0.w)),
                         fmaxf(fmaxf(v1.x, v1.y), fmaxf(v1.z, v1.w)));
        mx = fmaxf(mx, fmaxf(fmaxf(v2.x, v2.y), fmaxf(v2.z, v2.w)));
        mx = fmaxf(mx, fmaxf(fmaxf(v3.x, v3.y), fmaxf(v3.z, v3.w)));
        mx = fmaxf(mx, __shfl_xor_sync(0xFFFFFFFFu, mx, 1));
        mx = fmaxf(mx, __shfl_xor_sync(0xFFFFFFFFu, mx, 2));

        float f[16];
        f[0]  = __expf(v0.x - mx); f[1]  = __expf(v0.y - mx);
        f[2]  = __expf(v0.z - mx); f[3]  = __expf(v0.w - mx);
        f[4]  = __expf(v1.x - mx); f[5]  = __expf(v1.y - mx);
        f[6]  = __expf(v1.z - mx); f[7]  = __expf(v1.w - mx);
        f[8]  = __expf(v2.x - mx); f[9]  = __expf(v2.y - mx);
        f[10] = __expf(v2.z - mx); f[11] = __expf(v2.w - mx);
        f[12] = __expf(v3.x - mx); f[13] = __expf(v3.y - mx);
        f[14] = __expf(v3.z - mx); f[15] = __expf(v3.w - mx);

        float a = 0.f;
        #pragma unroll
        for (int i = 0; i < 16; i++) a += f[i];
        a += __shfl_xor_sync(0xFFFFFFFFu, a, 1);
        a += __shfl_xor_sync(0xFFFFFFFFu, a, 2);

        uint4 e0, e1;
        e0.x = f2h2(f[0], f[1]);   e0.y = f2h2(f[2], f[3]);
        e0.z = f2h2(f[4], f[5]);   e0.w = f2h2(f[6], f[7]);
        e1.x = f2h2(f[8], f[9]);   e1.y = f2h2(f[10], f[11]);
        e1.z = f2h2(f[12], f[13]); e1.w = f2h2(f[14], f[15]);
        uint4* dp = reinterpret_cast<uint4*>(g_e) + (size_t)row * 8 + q * 2;
        dp[0] = e0; dp[1] = e1;

        float rn = __fdividef(1.0f, a + EPSF);
        if (q == 0) g_r[row] = rn;
        acc16(e0, e1, rn, b);   // from quantized values (matches iteration reads)
    }
    FOLD8Q(b)
    tail_update_q(b, col_target, true);
}

// ---------------------------------------------------------------------------
// K2: one Sinkhorn iteration — cp.async 2-stage smem pipeline, 128-row tiles.
// Each thread processes 2 rows per tile (rit and rit+64), interleaved so the
// two rows' shuffle latencies overlap each other's FMA chains. g_r loads are
// hoisted before the pipeline wait. fp32 dot + fp32 accumulate (R6 numerics).
// ---------------------------------------------------------------------------
__global__ __launch_bounds__(NT, 3) void k_iter(int S, float col_target) {
    __shared__ __align__(16) unsigned char sm[STAGES * TILE_BYTES];
    __shared__ __align__(16) float sc[EXPERTS];
    int tid = threadIdx.x, lane = tid & 31, q = lane & 3;
    if (tid < EXPERTS) sc[tid] = g_c[tid];
    __syncthreads();

    float cq[16];
    #pragma unroll
    for (int i = 0; i < 16; i++) cq[i] = sc[q * 16 + i];
    float b[16];
    #pragma unroll
    for (int i = 0; i < 16; i++) b[i] = 0.f;

    int ntiles = S >> 7;                 // full 128-row tiles
    int grid   = gridDim.x;
    const char* ebase = reinterpret_cast<const char*>(g_e);
    int rit = tid >> 2;                  // row-in-tile (0..63); second row = +64

    // prologue: fill both stages (each thread copies 64B = 4 x 16B per stage)
    #pragma unroll
    for (int k = 0; k < STAGES; k++) {
        int t = blockIdx.x + k * grid;
        if (t < ntiles) {
            const char* src = ebase + (size_t)t * TILE_BYTES + tid * 16;
            char* dst = (char*)sm + k * TILE_BYTES + tid * 16;
            #pragma unroll
            for (int c = 0; c < 4; c++)
                __pipeline_memcpy_async(dst + c * 4096, src + c * 4096, 16);
        }
        __pipeline_commit();
    }

    int stage = 0;
    for (int t = blockIdx.x; t < ntiles; t += grid) {
        int rowA = (t << 7) + rit;
        int rowB = rowA + 64;
        float rA = g_r[rowA];            // issued before the wait
        float rB = g_r[rowB];

        __pipeline_wait_prior(STAGES - 1);
        __syncthreads();

        const uint4* tp = reinterpret_cast<const uint4*>(sm + stage * TILE_BYTES);
        uint4 a0 = tp[rit * 8 + q * 2];
        uint4 a1 = tp[rit * 8 + q * 2 + 1];
        uint4 c0 = tp[(rit + 64) * 8 + q * 2];
        uint4 c1 = tp[(rit + 64) * 8 + q * 2 + 1];

        float dA = dot16(a0, a1, cq);
        float dB = dot16(c0, c1, cq);
        dA += __shfl_xor_sync(0xFFFFFFFFu, dA, 1);
        dB += __shfl_xor_sync(0xFFFFFFFFu, dB, 1);
        dA += __shfl_xor_sync(0xFFFFFFFFu, dA, 2);
        dB += __shfl_xor_sync(0xFFFFFFFFu, dB, 2);

        float rnA = __fdividef(rA, fmaf(rA, dA, EPSF));
        float rnB = __fdividef(rB, fmaf(rB, dB, EPSF));
        if (q == 0) g_r[rowA] = rnA;
        if (q == 1) g_r[rowB] = rnB;
        acc16(a0, a1, rnA, b);
        acc16(c0, c1, rnB, b);

        __syncthreads();                 // stage fully consumed

        int tn = t + STAGES * grid;      // refill freed stage
        if (tn < ntiles) {
            const char* src = ebase + (size_t)tn * TILE_BYTES + tid * 16;
            char* dst = (char*)sm + stage * TILE_BYTES + tid * 16;
            #pragma unroll
            for (int c = 0; c < 4; c++)
                __pipeline_memcpy_async(dst + c * 4096, src + c * 4096, 16);
        }
        __pipeline_commit();
        stage ^= 1;
    }

    // tail rows (S % 128): uniform, predicated. Block 0 only.
    int rem0 = ntiles << 7;
    if (rem0 < S && blockIdx.x == 0) {
        #pragma unroll
        for (int h = 0; h < 2; h++) {
            int row = rem0 + rit + h * 64;
            bool ok = row < S;
            int rowc = ok ? row : (S - 1);
            const uint4* ep = reinterpret_cast<const uint4*>(g_e)
                              + (size_t)rowc * 8 + q * 2;
            uint4 e0 = ep[0], e1 = ep[1];
            float a = dot16(e0, e1, cq);
            a += __shfl_xor_sync(0xFFFFFFFFu, a, 1);
            a += __shfl_xor_sync(0xFFFFFFFFu, a, 2);
            float ri = g_r[rowc];
            float rn = ok ? __fdividef(ri, fmaf(ri, a, EPSF)) : 0.f;
            if (q == 0 && ok) g_r[rowc] = rn;
            acc16(e0, e1, rn, b);
        }
    }

    FOLD8Q(b)
    tail_update_q(b, col_target, false);
}

// ---------------------------------------------------------------------------
// K3: final (k == 2 fast path). Quad-split; fp32 ranking from logits (ldcs).
// Output float32: [idx (S*2)] then [weights (S*2)].
// ---------------------------------------------------------------------------
__global__ __launch_bounds__(NT, 3) void k_final2(const float* __restrict__ logits,
                                                  float* __restrict__ out, int S) {
    __shared__ __align__(16) float sc[EXPERTS];
    int tid = threadIdx.x, lane = tid & 31, q = lane & 3;
    if (tid < EXPERTS) sc[tid] = g_c[tid];
    __syncthreads();

    float cq[16];
    #pragma unroll
    for (int i = 0; i < 16; i++) cq[i] = sc[q * 16 + i];

    int gq = (blockIdx.x * NT + tid) >> 2;
    int nq = (NB * NT) >> 2;

    for (int row = gq; row < S; row += nq) {
        const float4* xp = reinterpret_cast<const float4*>(logits)
                           + (size_t)row * 16 + q * 4;
        float4 v0 = __ldcs(xp + 0), v1 = __ldcs(xp + 1);
        float4 v2 = __ldcs(xp + 2), v3 = __ldcs(xp + 3);
        float mx = fmaxf(fmaxf(fmaxf(v0.x, v0.y), fmaxf(v0.z, v0.w)),
                         fmaxf(fmaxf(v1.x, v1.y), fmaxf(v1.z, v1.w)));
        mx = fmaxf(mx, fmaxf(fmaxf(v2.x, v2.y), fmaxf(v2.z, v2.w)));
        mx = fmaxf(mx, fmaxf(fmaxf(v3.x, v3.y), fmaxf(v3.z, v3.w)));
        mx = fmaxf(mx, __shfl_xor_sync(0xFFFFFFFFu, mx, 1));
        mx = fmaxf(mx, __shfl_xor_sync(0xFFFFFFFFu, mx, 2));

        float u[16];
        u[0]  = __expf(v0.x - mx) * cq[0];  u[1]  = __expf(v0.y - mx) * cq[1];
        u[2]  = __expf(v0.z - mx) * cq[2];  u[3]  = __expf(v0.w - mx) * cq[3];
        u[4]  = __expf(v1.x - mx) * cq[4];  u[5]  = __expf(v1.y - mx) * cq[5];
        u[6]  = __expf(v1.z - mx) * cq[6];  u[7]  = __expf(v1.w - mx) * cq[7];
        u[8]  = __expf(v2.x - mx) * cq[8];  u[9]  = __expf(v2.y - mx) * cq[9];
        u[10] = __expf(v2.z - mx) * cq[10]; u[11] = __expf(v2.w - mx) * cq[11];
        u[12] = __expf(v3.x - mx) * cq[12]; u[13] = __expf(v3.y - mx) * cq[13];
        u[14] = __expf(v3.z - mx) * cq[14]; u[15] = __expf(v3.w - mx) * cq[15];

        float A = 0.f;
        float m1 = -1.f, m2 = -1.f, i1 = 0.f, i2 = 0.f;
        #pragma unroll
        for (int t = 0; t < 16; t++) {
            A += u[t];
            float jj = (float)(q * 16 + t);
            bool g1 = u[t] > m1, g2 = u[t] > m2;
            m2 = g1 ? m1 : (g2 ? u[t] : m2);
            i2 = g1 ? i1 : (g2 ? jj : i2);
            m1 = g1 ? u[t] : m1;
            i1 = g1 ? jj : i1;
        }
        A += __shfl_xor_sync(0xFFFFFFFFu, A, 1);
        A += __shfl_xor_sync(0xFFFFFFFFu, A, 2);

        #pragma unroll
        for (int o = 1; o <= 2; o <<= 1) {
            float om1 = __shfl_xor_sync(0xFFFFFFFFu, m1, o);
            float oi1 = __shfl_xor_sync(0xFFFFFFFFu, i1, o);
            float om2 = __shfl_xor_sync(0xFFFFFFFFu, m2, o);
            float oi2 = __shfl_xor_sync(0xFFFFFFFFu, i2, o);
            if (om1 > m1) {
                bool keep = (m1 >= om2);
                m2 = keep ? m1 : om2;
                i2 = keep ? i1 : oi2;
                m1 = om1; i1 = oi1;
            } else if (om1 > m2) {
                m2 = om1; i2 = oi1;
            }
        }

        if (q == 0) {
            float ri  = g_r[row];
            float t   = __fdividef(ri, fmaf(ri, A, EPSF));
            float w1  = m1 * t, w2 = m2 * t;
            float inv = __fdividef(1.0f, w1 + w2 + EPSF);
            reinterpret_cast<float2*>(out)[row] = make_float2(i1, i2);
            reinterpret_cast<float2*>(out)[(size_t)S + row] =
                make_float2(w1 * inv, w2 * inv);
        }
    }
}

// ---------------------------------------------------------------------------
// Generic fallback (k != 2): warp-per-row (known-correct R3 code)
// ---------------------------------------------------------------------------
__global__ void k_final_gen(const float* __restrict__ logits,
                            float* __restrict__ out, int S, int k, size_t out_n) {
    int lane = threadIdx.x & 31;
    int warp = (blockIdx.x * blockDim.x + threadIdx.x) >> 5;
    int nw   = (gridDim.x * blockDim.x) >> 5;
    float2 cc = ((const float2*)g_c)[lane];

    for (int row = warp; row < S; row += nw) {
        float2 x = ((const float2*)logits)[(size_t)row * 32 + lane];
        float m = fmaxf(x.x, x.y);
        #pragma unroll
        for (int o = 16; o; o >>= 1) m = fmaxf(m, __shfl_xor_sync(0xFFFFFFFFu, m, o));
        float u0 = __expf(x.x - m) * cc.x;
        float u1 = __expf(x.y - m) * cc.y;
        float A = u0 + u1;
        #pragma unroll
        for (int o = 16; o; o >>= 1) A += __shfl_xor_sync(0xFFFFFFFFu, A, o);
        float ri = g_r[row];
        float denom = ri * A + EPSF;
        float lu0 = u0, lu1 = u1;
        float vals[8]; int idxs[8];
        for (int t = 0; t < k; t++) {
            float lv; int li;
            if (lu0 >= lu1) { lv = lu0; li = 2 * lane; }
            else            { lv = lu1; li = 2 * lane + 1; }
            #pragma unroll
            for (int o = 16; o; o >>= 1) {
                float ov = __shfl_xor_sync(0xFFFFFFFFu, lv, o);
                int   oi = __shfl_xor_sync(0xFFFFFFFFu, li, o);
                if (ov > lv || (ov == lv && oi < li)) { lv = ov; li = oi; }
            }
            vals[t] = lv; idxs[t] = li;
            if (li == 2 * lane)     lu0 = -1.f;
            if (li == 2 * lane + 1) lu1 = -1.f;
        }
        if (lane == 0) {
            float v[8], vs = 0.f;
            for (int t = 0; t < k; t++) { v[t] = ri * vals[t] / denom; vs += v[t]; }
            float inv = 1.0f / (vs + EPSF);
            for (int t = 0; t < k; t++) {
                size_t pi = (size_t)row * k + t;
                size_t pw = (size_t)S * k + pi;
                if (pi < out_n) out[pi] = (float)idxs[t];
                if (pw < out_n) out[pw] = v[t] * inv;
            }
        }
    }
}

// ---------------------------------------------------------------------------
extern "C" void kernel_launch(void* const* d_in, const int* in_sizes, int n_in,
                              void* d_out, int out_size) {
    const float* logits = (const float*)d_in[0];
    float*       out    = (float*)d_out;

    int S = in_sizes[0] / EXPERTS;
    if (S > S_MAX) S = S_MAX;
    if (S < 1) S = 1;
    float col_target = (float)S / (float)EXPERTS;

    int k = (int)((size_t)out_size / (2 * (size_t)S));
    if (k < 1) k = 1;
    if (k > 8) k = 8;

    k_prep<<<NB, NT>>>(logits, S, col_target);          // includes iteration 1
    for (int it = 1; it < 10; it++)
        k_iter<<<NB, NT>>>(S, col_target);              // iterations 2..10
    if (k == 2)
        k_final2<<<NB, NT>>>(logits, out, S);
    else
        k_final_gen<<<4096, 256>>>(logits, out, S, k, (size_t)out_size);
}